// round 13
// baseline (speedup 1.0000x reference)
#include <cuda_runtime.h>
#include <math.h>

#define H_OUT 32
#define W_OUT 32
#define HX 128
#define WX 128
#define CH 32
#define BB 32
#define BP 64           // 8*8 objects
#define ROWS_PER_BLK 8  // h-quarter per block
#define NBLK (BB * BP * (H_OUT / ROWS_PER_BLK))   // 8192

// out elements = B*BP*H_OUT*W_OUT*CH
#define OUT_ELEMS (32ll*64*32*32*32)

__global__ void __launch_bounds__(256, 4)
stn_sample_kernel(const float* __restrict__ x,
                  const float* __restrict__ zw,
                  float* __restrict__ out,
                  float* __restrict__ mask)
{
    // blk = obj*4 + q ; obj = b*64 + p ; q selects 8 of 32 h rows
    int blk = blockIdx.x;
    int q   = blk & 3;
    int obj = blk >> 2;
    int p   = obj & 63;
    int b   = obj >> 6;
    int i   = p >> 3;
    int j   = p & 7;

    // ---- per-thread params (broadcast loads, no smem / no syncthreads) ----
    const float* zp = zw + (size_t)obj * 4;
    float z0 = __ldg(zp + 0);
    float z1 = __ldg(zp + 1);
    float z2 = __ldg(zp + 2);
    float z3 = __ldg(zp + 3);
    float sx = 0.5f / (1.0f + expf(-z0));
    float sy = 0.5f / (1.0f + expf(-z1));
    float bias_tx = 1.5f * (float)j / 7.0f - 0.75f;
    float bias_ty = 1.5f * (float)i / 7.0f - 0.75f;
    float tx = 0.5f * tanhf(z2) + bias_tx;
    float ty = 0.5f * tanhf(z3) + bias_ty;

    if (q == 0 && threadIdx.x == 0) {
        float bh  = sy * 0.5f;
        float bw  = sx * 0.5f;
        float bty = (ty + 1.0f) * 0.5f;
        float btx = (tx + 1.0f) * 0.5f;
        float* mp = mask + (size_t)obj * 4;
        mp[0] = bty - bh;
        mp[1] = btx - bw;
        mp[2] = bty + bh;
        mp[3] = btx + bw;
    }

    int tid  = threadIdx.x;       // 256 threads
    int half = tid >> 7;          // which of the 2 rows per iteration
    int r    = tid & 127;
    int c4   = r & 7;             // channel quad (low bits -> coalesced stores)
    int w0   = r >> 3;            // 0..15
    int w1   = w0 + 16;           // 16..31

    // ---- x-side for both w columns: invariant across h ----
    float xsA = -1.0f + 2.0f * (float)w0 / 31.0f;
    float xsB = -1.0f + 2.0f * (float)w1 / 31.0f;

    float pxA = 0.5f * (sx * xsA + tx + 1.0f) * (float)(WX - 1);
    float pxB = 0.5f * (sx * xsB + tx + 1.0f) * (float)(WX - 1);

    float xA0 = floorf(pxA), xA1 = xA0 + 1.0f;
    float xB0 = floorf(pxB), xB1 = xB0 + 1.0f;
    xA0 = fminf(fmaxf(xA0, 0.0f), (float)(WX - 1));
    xA1 = fminf(fmaxf(xA1, 0.0f), (float)(WX - 1));
    xB0 = fminf(fmaxf(xB0, 0.0f), (float)(WX - 1));
    xB1 = fminf(fmaxf(xB1, 0.0f), (float)(WX - 1));

    float wxA0 = xA1 - pxA, wxA1 = pxA - xA0;
    float wxB0 = xB1 - pxB, wxB1 = pxB - xB0;

    int colA0 = (int)xA0 * (CH / 4) + c4;
    int colA1 = (int)xA1 * (CH / 4) + c4;
    int colB0 = (int)xB0 * (CH / 4) + c4;
    int colB1 = (int)xB1 * (CH / 4) + c4;

    const float4* __restrict__ img =
        (const float4*)(x + (size_t)b * HX * WX * CH);
    float4* __restrict__ op =
        (float4*)out + (size_t)obj * (H_OUT * W_OUT * (CH / 4))
                     + (size_t)q * (ROWS_PER_BLK * W_OUT * (CH / 4));

#pragma unroll
    for (int t = 0; t < ROWS_PER_BLK / 2; t++) {
        int hh = t * 2 + half;            // row within this block's quarter
        int h  = q * ROWS_PER_BLK + hh;   // global output row

        float ys = -1.0f + 2.0f * (float)h / 31.0f;
        float gy = sy * ys + ty;
        float py = 0.5f * (gy + 1.0f) * (float)(HX - 1);
        float y0 = floorf(py), y1 = y0 + 1.0f;
        y0 = fminf(fmaxf(y0, 0.0f), (float)(HX - 1));
        y1 = fminf(fmaxf(y1, 0.0f), (float)(HX - 1));
        float wy0 = y1 - py;
        float wy1 = py - y0;

        int row0 = (int)y0 * (WX * (CH / 4));
        int row1 = (int)y1 * (WX * (CH / 4));

        // 8 independent loads in flight
        float4 IaA = img[row0 + colA0];
        float4 IbA = img[row1 + colA0];
        float4 IcA = img[row0 + colA1];
        float4 IdA = img[row1 + colA1];
        float4 IaB = img[row0 + colB0];
        float4 IbB = img[row1 + colB0];
        float4 IcB = img[row0 + colB1];
        float4 IdB = img[row1 + colB1];

        float waA = wxA0 * wy0, wbA = wxA0 * wy1;
        float wcA = wxA1 * wy0, wdA = wxA1 * wy1;
        float waB = wxB0 * wy0, wbB = wxB0 * wy1;
        float wcB = wxB1 * wy0, wdB = wxB1 * wy1;

        float4 oA, oB;
        oA.x = waA * IaA.x + wbA * IbA.x + wcA * IcA.x + wdA * IdA.x;
        oA.y = waA * IaA.y + wbA * IbA.y + wcA * IcA.y + wdA * IdA.y;
        oA.z = waA * IaA.z + wbA * IbA.z + wcA * IcA.z + wdA * IdA.z;
        oA.w = waA * IaA.w + wbA * IbA.w + wcA * IcA.w + wdA * IdA.w;
        oB.x = waB * IaB.x + wbB * IbB.x + wcB * IcB.x + wdB * IdB.x;
        oB.y = waB * IaB.y + wbB * IbB.y + wcB * IcB.y + wdB * IdB.y;
        oB.z = waB * IaB.z + wbB * IbB.z + wcB * IcB.z + wdB * IdB.z;
        oB.w = waB * IaB.w + wbB * IbB.w + wcB * IcB.w + wdB * IdB.w;

        // stores: lanes (4 w × 8 c4) -> 512B over 4 lines, fully coalesced
        float4* orow = op + (size_t)hh * (W_OUT * (CH / 4));
        __stcs(&orow[w0 * (CH / 4) + c4], oA);
        __stcs(&orow[w1 * (CH / 4) + c4], oB);
    }
}

extern "C" void kernel_launch(void* const* d_in, const int* in_sizes, int n_in,
                              void* d_out, int out_size)
{
    const float* x  = (const float*)d_in[0];
    const float* zw = (const float*)d_in[1];
    float* out = (float*)d_out;

    stn_sample_kernel<<<NBLK, 256>>>(x, zw, out, out + OUT_ELEMS);
}

// round 15
// speedup vs baseline: 1.0496x; 1.0496x over previous
#include <cuda_runtime.h>
#include <math.h>

#define H_OUT 32
#define W_OUT 32
#define HX 128
#define WX 128
#define CH 32
#define BB 32
#define BP 64            // 8*8 objects
#define ROWS_PER_BLK 16  // h-half per block
#define NBLK (BB * BP * (H_OUT / ROWS_PER_BLK))   // 4096

// out elements = B*BP*H_OUT*W_OUT*CH
#define OUT_ELEMS (32ll*64*32*32*32)

__global__ void __launch_bounds__(256, 4)
stn_sample_kernel(const float* __restrict__ x,
                  const float* __restrict__ zw,
                  float* __restrict__ out,
                  float* __restrict__ mask)
{
    // blk = obj*2 + q ; obj = b*64 + p ; q selects 16 of 32 h rows
    int blk = blockIdx.x;
    int q   = blk & 1;
    int obj = blk >> 1;
    int p   = obj & 63;
    int b   = obj >> 6;
    int i   = p >> 3;
    int j   = p & 7;

    // ---- per-thread params (broadcast loads, no smem / no syncthreads) ----
    const float* zp = zw + (size_t)obj * 4;
    float z0 = __ldg(zp + 0);
    float z1 = __ldg(zp + 1);
    float z2 = __ldg(zp + 2);
    float z3 = __ldg(zp + 3);
    float sx = 0.5f / (1.0f + expf(-z0));
    float sy = 0.5f / (1.0f + expf(-z1));
    float bias_tx = 1.5f * (float)j / 7.0f - 0.75f;
    float bias_ty = 1.5f * (float)i / 7.0f - 0.75f;
    float tx = 0.5f * tanhf(z2) + bias_tx;
    float ty = 0.5f * tanhf(z3) + bias_ty;

    if (q == 0 && threadIdx.x == 0) {
        float bh  = sy * 0.5f;
        float bw  = sx * 0.5f;
        float bty = (ty + 1.0f) * 0.5f;
        float btx = (tx + 1.0f) * 0.5f;
        float* mp = mask + (size_t)obj * 4;
        mp[0] = bty - bh;
        mp[1] = btx - bw;
        mp[2] = bty + bh;
        mp[3] = btx + bw;
    }

    int tid = threadIdx.x;      // 256 threads
    int c4  = tid & 7;          // channel quad 0..7 (4 floats each)
    int w   = tid >> 3;         // 0..31

    // ---- x-side: invariant across h ----
    float xs = -1.0f + 2.0f * (float)w / 31.0f;
    float gx = sx * xs + tx;
    float px = 0.5f * (gx + 1.0f) * (float)(WX - 1);
    float x0 = floorf(px), x1 = x0 + 1.0f;
    x0 = fminf(fmaxf(x0, 0.0f), (float)(WX - 1));
    x1 = fminf(fmaxf(x1, 0.0f), (float)(WX - 1));
    float wx0 = x1 - px;
    float wx1 = px - x0;
    int col0 = (int)x0 * (CH / 4) + c4;
    int col1 = (int)x1 * (CH / 4) + c4;

    const float4* __restrict__ img =
        (const float4*)(x + (size_t)b * HX * WX * CH);
    float4* __restrict__ op =
        (float4*)out + (size_t)obj * (H_OUT * W_OUT * (CH / 4))
                     + (size_t)q * (ROWS_PER_BLK * W_OUT * (CH / 4));

#pragma unroll
    for (int hh = 0; hh < ROWS_PER_BLK; hh++) {
        int h = q * ROWS_PER_BLK + hh;
        float ys = -1.0f + 2.0f * (float)h / 31.0f;
        float gy = sy * ys + ty;
        float py = 0.5f * (gy + 1.0f) * (float)(HX - 1);
        float y0 = floorf(py), y1 = y0 + 1.0f;
        y0 = fminf(fmaxf(y0, 0.0f), (float)(HX - 1));
        y1 = fminf(fmaxf(y1, 0.0f), (float)(HX - 1));
        float wy0 = y1 - py;
        float wy1 = py - y0;

        int row0 = (int)y0 * (WX * (CH / 4));
        int row1 = (int)y1 * (WX * (CH / 4));

        float4 Ia = img[row0 + col0];
        float4 Ib = img[row1 + col0];
        float4 Ic = img[row0 + col1];
        float4 Id = img[row1 + col1];

        float wa = wx0 * wy0;
        float wb = wx0 * wy1;
        float wc = wx1 * wy0;
        float wd = wx1 * wy1;

        float4 o;
        o.x = wa * Ia.x + wb * Ib.x + wc * Ic.x + wd * Id.x;
        o.y = wa * Ia.y + wb * Ib.y + wc * Ic.y + wd * Id.y;
        o.z = wa * Ia.z + wb * Ib.z + wc * Ic.z + wd * Id.z;
        o.w = wa * Ia.w + wb * Ib.w + wc * Ic.w + wd * Id.w;

        // w*8 + c4 == tid -> fully coalesced; streaming store (never re-read)
        __stcs(&op[hh * (W_OUT * (CH / 4)) + tid], o);
    }
}

extern "C" void kernel_launch(void* const* d_in, const int* in_sizes, int n_in,
                              void* d_out, int out_size)
{
    const float* x  = (const float*)d_in[0];
    const float* zw = (const float*)d_in[1];
    float* out = (float*)d_out;

    stn_sample_kernel<<<NBLK, 256>>>(x, zw, out, out + OUT_ELEMS);
}